// round 4
// baseline (speedup 1.0000x reference)
#include <cuda_runtime.h>

#define CH 64
#define MMAX 50000
#define EMAX 800000

// Allocation-free scratch.
__device__ float4 g_S4[MMAX * (CH / 4)];
__device__ float  g_deg[MMAX];
__device__ int    g_cnt[MMAX];
__device__ int    g_off[MMAX + 1];
__device__ int    g_pos[MMAX];
__device__ int    g_csrc[EMAX];
__device__ float  g_cew[EMAX];

__global__ void zero_cnt_kernel(int M) {
    int i = blockIdx.x * blockDim.x + threadIdx.x;
    if (i < M) g_cnt[i] = 0;
}

__global__ void hist_kernel(const int* __restrict__ idx1, int E) {
    int e = blockIdx.x * blockDim.x + threadIdx.x;
    if (e < E) atomicAdd(&g_cnt[idx1[e]], 1);
}

// Single-block exclusive scan of g_cnt[0..M) -> g_off / g_pos; g_off[M] = E.
__global__ __launch_bounds__(1024) void scan_kernel(int M, int E) {
    __shared__ int part[1024];
    int t = threadIdx.x;
    int chunk = (M + 1023) >> 10;
    int lo = t * chunk;
    int hi = lo + chunk; if (hi > M) hi = M; if (lo > M) lo = M;
    int s = 0;
    for (int i = lo; i < hi; i++) s += g_cnt[i];
    part[t] = s;
    __syncthreads();
    // Hillis-Steele inclusive scan over 1024 partials
    for (int d = 1; d < 1024; d <<= 1) {
        int v = part[t];
        int o = (t >= d) ? part[t - d] : 0;
        __syncthreads();
        part[t] = v + o;
        __syncthreads();
    }
    int off = (t == 0) ? 0 : part[t - 1];   // exclusive
    for (int i = lo; i < hi; i++) {
        g_off[i] = off;
        g_pos[i] = off;
        off += g_cnt[i];
    }
    if (t == 0) g_off[M] = E;
}

__global__ void fill_kernel(const int* __restrict__ idx,
                            const int* __restrict__ idx1,
                            const float* __restrict__ ew,
                            int E) {
    int e = blockIdx.x * blockDim.x + threadIdx.x;
    if (e >= E) return;
    int dst = idx1[e];
    int slot = atomicAdd(&g_pos[dst], 1);
    g_csrc[slot] = idx[e];
    g_cew[slot] = ew[e];
}

// One warp per segment: lane l accumulates columns {2l, 2l+1} over all of the
// segment's source rows (register accumulation — zero atomics), plus weighted
// degree. src indices prefetched one iteration ahead to overlap L2 latency.
__global__ __launch_bounds__(256) void seg_kernel(const float2* __restrict__ A2,
                                                  int M) {
    int w = (blockIdx.x * blockDim.x + threadIdx.x) >> 5;
    int l = threadIdx.x & 31;
    if (w >= M) return;
    int start = g_off[w];
    int end   = g_off[w + 1];

    float ax = 0.f, ay = 0.f, dacc = 0.f;
    int src = (start < end) ? g_csrc[start] : 0;
    for (int j = start; j < end; j++) {
        int nsrc = (j + 1 < end) ? g_csrc[j + 1] : 0;
        float wgt = g_cew[j];
        float2 v = __ldg(&A2[src * 32 + l]);
        ax += v.x; ay += v.y;
        dacc += wgt;
        src = nsrc;
    }
    ((float2*)g_S4)[w * 32 + l] = make_float2(ax, ay);
    if (l == 0) g_deg[w] = dacc;
}

// Epilogue: out[m,c] = deg[m]*(x·W1[c,:] + b1[c]) + S[m,:]·weight[:,c]
//                      + x·W2[c,:] + b2[c],  x = A[valid_nodes[m],:]
__global__ __launch_bounds__(256) void final_kernel(
        const float* __restrict__ A,
        const int* __restrict__ vn,
        const float* __restrict__ W1,
        const float* __restrict__ b1,
        const float* __restrict__ W2,
        const float* __restrict__ b2,
        const float* __restrict__ Wt,   // weight, layout [k][c]
        float* __restrict__ out,
        int M) {
    __shared__ float sW1[CH * CH];   // transposed: [k][c]
    __shared__ float sW2[CH * CH];   // transposed: [k][c]
    __shared__ float sW [CH * CH];   // weight already [k][c]

    int tid = threadIdx.x;
    for (int i = tid; i < CH * CH; i += 256) {
        int c = i >> 6, k = i & 63;          // W1/W2 are [c][k]
        sW1[k * CH + c] = W1[i];
        sW2[k * CH + c] = W2[i];
        sW[i] = Wt[i];
    }

    int c  = tid & 63;
    int g  = tid >> 6;
    float b1c = __ldg(&b1[c]);
    float b2c = __ldg(&b2[c]);
    __syncthreads();

    int m0 = blockIdx.x * 16 + g * 4;
    if (m0 >= M) return;

    const float4* A4 = (const float4*)A;

    int row[4];
    bool ok[4];
    #pragma unroll
    for (int r = 0; r < 4; r++) {
        ok[r] = (m0 + r) < M;
        row[r] = ok[r] ? vn[m0 + r] : 0;
    }

    float s1[4] = {0.f, 0.f, 0.f, 0.f};
    float s2[4] = {0.f, 0.f, 0.f, 0.f};
    float s3[4] = {0.f, 0.f, 0.f, 0.f};

    #pragma unroll
    for (int kk = 0; kk < 16; kk++) {
        float w1v[4], w2v[4], wv[4];
        #pragma unroll
        for (int j = 0; j < 4; j++) {
            int k = kk * 4 + j;
            w1v[j] = sW1[k * CH + c];
            w2v[j] = sW2[k * CH + c];
            wv[j]  = sW [k * CH + c];
        }
        #pragma unroll
        for (int r = 0; r < 4; r++) {
            float4 x = __ldg(&A4[row[r] * 16 + kk]);
            float4 s = g_S4[(m0 + r) * 16 + kk];
            s1[r] += x.x * w1v[0] + x.y * w1v[1] + x.z * w1v[2] + x.w * w1v[3];
            s2[r] += x.x * w2v[0] + x.y * w2v[1] + x.z * w2v[2] + x.w * w2v[3];
            s3[r] += s.x * wv[0]  + s.y * wv[1]  + s.z * wv[2]  + s.w * wv[3];
        }
    }

    #pragma unroll
    for (int r = 0; r < 4; r++) {
        if (ok[r]) {
            float d = g_deg[m0 + r];
            out[(m0 + r) * CH + c] =
                d * (s1[r] + b1c) + s3[r] + s2[r] + b2c;
        }
    }
}

extern "C" void kernel_launch(void* const* d_in, const int* in_sizes, int n_in,
                              void* d_out, int out_size) {
    const float* A    = (const float*)d_in[0];   // [N, 64] f32
    const int*   vn   = (const int*)d_in[1];     // [M] int32
    const int*   idx  = (const int*)d_in[2];     // [E] int32
    const int*   idx1 = (const int*)d_in[3];     // [E] int32
    const float* ew   = (const float*)d_in[4];   // [E] f32
    const float* Wt   = (const float*)d_in[5];   // [64, 64] = [CIN][COUT]
    const float* W1   = (const float*)d_in[6];   // [64, 64] = [COUT][CIN]
    const float* b1   = (const float*)d_in[7];   // [64]
    const float* W2   = (const float*)d_in[8];   // [64, 64]
    const float* b2   = (const float*)d_in[9];   // [64]
    float* out = (float*)d_out;

    int M = in_sizes[1];
    int E = in_sizes[2];

    int blocksM = (M + 255) / 256;
    int blocksE = (E + 255) / 256;

    zero_cnt_kernel<<<blocksM, 256>>>(M);
    hist_kernel<<<blocksE, 256>>>(idx1, E);
    scan_kernel<<<1, 1024>>>(M, E);
    fill_kernel<<<blocksE, 256>>>(idx, idx1, ew, E);
    {
        int warps = M;
        int blocks = (warps * 32 + 255) / 256;
        seg_kernel<<<blocks, 256>>>((const float2*)A, M);
    }
    {
        int blocks = (M + 15) / 16;
        final_kernel<<<blocks, 256>>>(A, vn, W1, b1, W2, b2, Wt, out, M);
    }
}

// round 5
// speedup vs baseline: 1.4152x; 1.4152x over previous
#include <cuda_runtime.h>

#define CH 64
#define MMAX 50000
#define CAP 80

// Allocation-free scratch.
__device__ float4 g_S4[MMAX * (CH / 4)];   // segment sums [M][64]
__device__ float  g_deg[MMAX];
__device__ int    g_cnt[MMAX];
__device__ int2   g_bin[MMAX * CAP];       // {src, __float_as_int(ew)}

__global__ void zero_kernel(int M) {
    int i = blockIdx.x * blockDim.x + threadIdx.x;
    if (i < M * (CH / 4)) g_S4[i] = make_float4(0.f, 0.f, 0.f, 0.f);
    if (i < M) { g_cnt[i] = 0; g_deg[i] = 0.f; }
}

// Bin each edge under its destination. Packed 8B store (src + ew bits).
// Overflow (never expected at CAP=80, max observed degree ~35) falls back to
// guaranteed-correct vector atomics into g_S / g_deg.
__global__ void fill_kernel(const float4* __restrict__ A4,
                            const int* __restrict__ idx,
                            const int* __restrict__ idx1,
                            const float* __restrict__ ew,
                            int E) {
    int e = blockIdx.x * blockDim.x + threadIdx.x;
    if (e >= E) return;
    int dst = idx1[e];
    int slot = atomicAdd(&g_cnt[dst], 1);
    if (slot < CAP) {
        g_bin[dst * CAP + slot] = make_int2(idx[e], __float_as_int(ew[e]));
    } else {
        int src = idx[e];
        #pragma unroll
        for (int q = 0; q < 16; q++) {
            float4 v = __ldg(&A4[src * 16 + q]);
            float4* p = &g_S4[dst * 16 + q];
            asm volatile("red.global.add.v4.f32 [%0], {%1,%2,%3,%4};"
                         :: "l"(p), "f"(v.x), "f"(v.y), "f"(v.z), "f"(v.w)
                         : "memory");
        }
        atomicAdd(&g_deg[dst], __ldg(&ew[e]));
    }
}

// One warp per segment. Bin entries loaded with ONE coalesced int2 load per
// 32-chunk; src broadcast to the warp via shfl. Inner loop = pure pipelined
// 256B row gathers from L2 + register FADDs. No atomics.
__global__ __launch_bounds__(256) void seg_kernel(const float2* __restrict__ A2,
                                                  int M) {
    int w = (blockIdx.x * blockDim.x + threadIdx.x) >> 5;
    int l = threadIdx.x & 31;
    if (w >= M) return;
    int cntRaw = g_cnt[w];
    bool ovf = cntRaw > CAP;
    int cnt = ovf ? CAP : cntRaw;

    float ax = 0.f, ay = 0.f, dl = 0.f;
    for (int c0 = 0; c0 < cnt; c0 += 32) {
        int nn = cnt - c0; if (nn > 32) nn = 32;
        int2 b = (l < nn) ? __ldg(&g_bin[w * CAP + c0 + l]) : make_int2(0, 0);
        if (l < nn) dl += __int_as_float(b.y);
        for (int j = 0; j < nn; j++) {
            int src = __shfl_sync(0xffffffffu, b.x, j);
            float2 v = __ldg(&A2[src * 32 + l]);
            ax += v.x; ay += v.y;
        }
    }
    #pragma unroll
    for (int o = 16; o; o >>= 1) dl += __shfl_xor_sync(0xffffffffu, dl, o);

    float2* S2 = (float2*)g_S4;
    if (ovf) {
        float2 old = S2[w * 32 + l];
        ax += old.x; ay += old.y;
        if (l == 0) dl += g_deg[w];
    }
    S2[w * 32 + l] = make_float2(ax, ay);
    if (l == 0) g_deg[w] = dl;
}

// Epilogue: out[m,c] = deg[m]*(x·W1[c,:] + b1[c]) + S[m,:]·weight[:,c]
//                      + x·W2[c,:] + b2[c],  x = A[valid_nodes[m],:]
__global__ __launch_bounds__(256) void final_kernel(
        const float* __restrict__ A,
        const int* __restrict__ vn,
        const float* __restrict__ W1,
        const float* __restrict__ b1,
        const float* __restrict__ W2,
        const float* __restrict__ b2,
        const float* __restrict__ Wt,   // weight, layout [k][c]
        float* __restrict__ out,
        int M) {
    __shared__ float sW1[CH * CH];   // transposed: [k][c]
    __shared__ float sW2[CH * CH];   // transposed: [k][c]
    __shared__ float sW [CH * CH];   // weight already [k][c]

    int tid = threadIdx.x;
    for (int i = tid; i < CH * CH; i += 256) {
        int c = i >> 6, k = i & 63;          // W1/W2 are [c][k]
        sW1[k * CH + c] = W1[i];
        sW2[k * CH + c] = W2[i];
        sW[i] = Wt[i];
    }

    int c  = tid & 63;
    int g  = tid >> 6;
    float b1c = __ldg(&b1[c]);
    float b2c = __ldg(&b2[c]);
    __syncthreads();

    int m0 = blockIdx.x * 16 + g * 4;
    if (m0 >= M) return;

    const float4* A4 = (const float4*)A;

    int row[4];
    bool ok[4];
    #pragma unroll
    for (int r = 0; r < 4; r++) {
        ok[r] = (m0 + r) < M;
        row[r] = ok[r] ? vn[m0 + r] : 0;
    }

    float s1[4] = {0.f, 0.f, 0.f, 0.f};
    float s2[4] = {0.f, 0.f, 0.f, 0.f};
    float s3[4] = {0.f, 0.f, 0.f, 0.f};

    #pragma unroll
    for (int kk = 0; kk < 16; kk++) {
        float w1v[4], w2v[4], wv[4];
        #pragma unroll
        for (int j = 0; j < 4; j++) {
            int k = kk * 4 + j;
            w1v[j] = sW1[k * CH + c];
            w2v[j] = sW2[k * CH + c];
            wv[j]  = sW [k * CH + c];
        }
        #pragma unroll
        for (int r = 0; r < 4; r++) {
            float4 x = __ldg(&A4[row[r] * 16 + kk]);
            float4 s = g_S4[(m0 + r) * 16 + kk];
            s1[r] += x.x * w1v[0] + x.y * w1v[1] + x.z * w1v[2] + x.w * w1v[3];
            s2[r] += x.x * w2v[0] + x.y * w2v[1] + x.z * w2v[2] + x.w * w2v[3];
            s3[r] += s.x * wv[0]  + s.y * wv[1]  + s.z * wv[2]  + s.w * wv[3];
        }
    }

    #pragma unroll
    for (int r = 0; r < 4; r++) {
        if (ok[r]) {
            float d = g_deg[m0 + r];
            out[(m0 + r) * CH + c] =
                d * (s1[r] + b1c) + s3[r] + s2[r] + b2c;
        }
    }
}

extern "C" void kernel_launch(void* const* d_in, const int* in_sizes, int n_in,
                              void* d_out, int out_size) {
    const float* A    = (const float*)d_in[0];   // [N, 64] f32
    const int*   vn   = (const int*)d_in[1];     // [M] int32
    const int*   idx  = (const int*)d_in[2];     // [E] int32
    const int*   idx1 = (const int*)d_in[3];     // [E] int32
    const float* ew   = (const float*)d_in[4];   // [E] f32
    const float* Wt   = (const float*)d_in[5];   // [64, 64] = [CIN][COUT]
    const float* W1   = (const float*)d_in[6];   // [64, 64] = [COUT][CIN]
    const float* b1   = (const float*)d_in[7];   // [64]
    const float* W2   = (const float*)d_in[8];   // [64, 64]
    const float* b2   = (const float*)d_in[9];   // [64]
    float* out = (float*)d_out;

    int M = in_sizes[1];
    int E = in_sizes[2];

    {
        int total = M * (CH / 4);
        zero_kernel<<<(total + 255) / 256, 256>>>(M);
    }
    fill_kernel<<<(E + 255) / 256, 256>>>((const float4*)A, idx, idx1, ew, E);
    {
        int blocks = (M * 32 + 255) / 256;
        seg_kernel<<<blocks, 256>>>((const float2*)A, M);
    }
    {
        int blocks = (M + 15) / 16;
        final_kernel<<<blocks, 256>>>(A, vn, W1, b1, W2, b2, Wt, out, M);
    }
}

// round 6
// speedup vs baseline: 3.4591x; 2.4444x over previous
#include <cuda_runtime.h>

#define CH 64
#define MMAX 50000
#define CAP 80
#define TILE_M 32

// Allocation-free scratch.
__device__ float4 g_S4[MMAX * (CH / 4)];   // segment sums [M][64]
__device__ float  g_deg[MMAX];
__device__ int    g_cnt[MMAX];
__device__ int2   g_bin[MMAX * CAP];       // {src, __float_as_int(ew)}

__global__ void zero_kernel(int M) {
    int i = blockIdx.x * blockDim.x + threadIdx.x;
    if (i < M * (CH / 4)) g_S4[i] = make_float4(0.f, 0.f, 0.f, 0.f);
    if (i < M) { g_cnt[i] = 0; g_deg[i] = 0.f; }
}

// Bin each edge under its destination. Packed 8B store (src + ew bits).
// Overflow (not expected at CAP=80) falls back to correct vector atomics.
__global__ void fill_kernel(const float4* __restrict__ A4,
                            const int* __restrict__ idx,
                            const int* __restrict__ idx1,
                            const float* __restrict__ ew,
                            int E) {
    int e = blockIdx.x * blockDim.x + threadIdx.x;
    if (e >= E) return;
    int dst = idx1[e];
    int slot = atomicAdd(&g_cnt[dst], 1);
    if (slot < CAP) {
        g_bin[dst * CAP + slot] = make_int2(idx[e], __float_as_int(ew[e]));
    } else {
        int src = idx[e];
        #pragma unroll
        for (int q = 0; q < 16; q++) {
            float4 v = __ldg(&A4[src * 16 + q]);
            float4* p = &g_S4[dst * 16 + q];
            asm volatile("red.global.add.v4.f32 [%0], {%1,%2,%3,%4};"
                         :: "l"(p), "f"(v.x), "f"(v.y), "f"(v.z), "f"(v.w)
                         : "memory");
        }
        atomicAdd(&g_deg[dst], __ldg(&ew[e]));
    }
}

// One warp per segment. Bin entries loaded with ONE coalesced int2 load per
// 32-chunk; src broadcast via shfl. Inner loop = pipelined 256B row gathers
// from L2 + register FADDs. No atomics.
__global__ __launch_bounds__(256) void seg_kernel(const float2* __restrict__ A2,
                                                  int M) {
    int w = (blockIdx.x * blockDim.x + threadIdx.x) >> 5;
    int l = threadIdx.x & 31;
    if (w >= M) return;
    int cntRaw = g_cnt[w];
    bool ovf = cntRaw > CAP;
    int cnt = ovf ? CAP : cntRaw;

    float ax = 0.f, ay = 0.f, dl = 0.f;
    for (int c0 = 0; c0 < cnt; c0 += 32) {
        int nn = cnt - c0; if (nn > 32) nn = 32;
        int2 b = (l < nn) ? __ldg(&g_bin[w * CAP + c0 + l]) : make_int2(0, 0);
        if (l < nn) dl += __int_as_float(b.y);
        for (int j = 0; j < nn; j++) {
            int src = __shfl_sync(0xffffffffu, b.x, j);
            float2 v = __ldg(&A2[src * 32 + l]);
            ax += v.x; ay += v.y;
        }
    }
    #pragma unroll
    for (int o = 16; o; o >>= 1) dl += __shfl_xor_sync(0xffffffffu, dl, o);

    float2* S2 = (float2*)g_S4;
    if (ovf) {
        float2 old = S2[w * 32 + l];
        ax += old.x; ay += old.y;
        if (l == 0) dl += g_deg[w];
    }
    S2[w * 32 + l] = make_float2(ax, ay);
    if (l == 0) g_deg[w] = dl;
}

// Epilogue: out[m,c] = deg[m]*(x·W1[c,:] + b1[c]) + S[m,:]·weight[:,c]
//                      + x·W2[c,:] + b2[c],  x = A[valid_nodes[m],:]
// Grid-stride over 32-row tiles; weights in smem once per block (vectorized
// float4 layouts), X/S staged per tile, 8-row register blocking per thread.
__global__ __launch_bounds__(256) void final_kernel(
        const float4* __restrict__ A4,
        const int* __restrict__ vn,
        const float* __restrict__ W1,
        const float* __restrict__ b1,
        const float* __restrict__ W2,
        const float* __restrict__ b2,
        const float* __restrict__ Wt,   // weight, layout [k][c]
        float* __restrict__ out,
        int M, int numTiles) {
    extern __shared__ float4 sm[];
    float4* sW1v = sm;                   // [16][64]: kk -> W1[c][4kk..4kk+3]
    float4* sW2v = sm + 1024;            // [16][64]
    float4* sWv  = sm + 2048;            // [16][64]: kk -> Wt[4kk..4kk+3][c]
    float4* sX   = sm + 3072;            // [32][16]
    float4* sS   = sm + 3584;            // [32][16]
    float*  sDeg = (float*)(sm + 4096);  // [32]

    int tid = threadIdx.x;
    int c = tid & 63;
    int g = tid >> 6;
    float b1c = __ldg(&b1[c]);
    float b2c = __ldg(&b2[c]);

    // One-time weight fill (amortized over all tiles this block handles).
    const float4* W1v4 = (const float4*)W1;
    const float4* W2v4 = (const float4*)W2;
    for (int i = tid; i < 1024; i += 256) {
        int kk = i >> 6, cc = i & 63;
        sW1v[i] = __ldg(&W1v4[cc * 16 + kk]);   // W1 is [c][k] row-major
        sW2v[i] = __ldg(&W2v4[cc * 16 + kk]);
        int k0 = kk * 4;
        sWv[i] = make_float4(__ldg(&Wt[(k0 + 0) * CH + cc]),
                             __ldg(&Wt[(k0 + 1) * CH + cc]),
                             __ldg(&Wt[(k0 + 2) * CH + cc]),
                             __ldg(&Wt[(k0 + 3) * CH + cc]));
    }

    for (int tile = blockIdx.x; tile < numTiles; tile += gridDim.x) {
        int m0 = tile * TILE_M;
        __syncthreads();   // protect staging buffers from previous iteration
        // Stage X (gathered via vn) and S, coalesced.
        for (int i = tid; i < TILE_M * 16; i += 256) {
            int r = i >> 4, q = i & 15;
            int m = m0 + r;
            int mc = (m < M) ? m : 0;
            int rowA = (m < M) ? vn[m] : 0;
            sX[i] = __ldg(&A4[rowA * 16 + q]);
            sS[i] = g_S4[mc * 16 + q];
        }
        if (tid < TILE_M) {
            int m = m0 + tid;
            sDeg[tid] = (m < M) ? g_deg[m] : 0.f;
        }
        __syncthreads();

        float s1[8], s2[8], s3[8];
        #pragma unroll
        for (int r = 0; r < 8; r++) { s1[r] = 0.f; s2[r] = 0.f; s3[r] = 0.f; }

        #pragma unroll
        for (int kk = 0; kk < 16; kk++) {
            float4 w1 = sW1v[kk * 64 + c];
            float4 w2 = sW2v[kk * 64 + c];
            float4 wv = sWv [kk * 64 + c];
            #pragma unroll
            for (int r = 0; r < 8; r++) {
                float4 x = sX[(g * 8 + r) * 16 + kk];   // warp-broadcast
                float4 s = sS[(g * 8 + r) * 16 + kk];
                s1[r] += x.x * w1.x + x.y * w1.y + x.z * w1.z + x.w * w1.w;
                s2[r] += x.x * w2.x + x.y * w2.y + x.z * w2.z + x.w * w2.w;
                s3[r] += s.x * wv.x + s.y * wv.y + s.z * wv.z + s.w * wv.w;
            }
        }

        #pragma unroll
        for (int r = 0; r < 8; r++) {
            int m = m0 + g * 8 + r;
            if (m < M) {
                float d = sDeg[g * 8 + r];
                out[m * CH + c] = d * (s1[r] + b1c) + s3[r] + s2[r] + b2c;
            }
        }
    }
}

extern "C" void kernel_launch(void* const* d_in, const int* in_sizes, int n_in,
                              void* d_out, int out_size) {
    const float* A    = (const float*)d_in[0];   // [N, 64] f32
    const int*   vn   = (const int*)d_in[1];     // [M] int32
    const int*   idx  = (const int*)d_in[2];     // [E] int32
    const int*   idx1 = (const int*)d_in[3];     // [E] int32
    const float* ew   = (const float*)d_in[4];   // [E] f32
    const float* Wt   = (const float*)d_in[5];   // [64, 64] = [CIN][COUT]
    const float* W1   = (const float*)d_in[6];   // [64, 64] = [COUT][CIN]
    const float* b1   = (const float*)d_in[7];   // [64]
    const float* W2   = (const float*)d_in[8];   // [64, 64]
    const float* b2   = (const float*)d_in[9];   // [64]
    float* out = (float*)d_out;

    int M = in_sizes[1];
    int E = in_sizes[2];

    {
        int total = M * (CH / 4);
        zero_kernel<<<(total + 255) / 256, 256>>>(M);
    }
    fill_kernel<<<(E + 255) / 256, 256>>>((const float4*)A, idx, idx1, ew, E);
    {
        int blocks = (M * 32 + 255) / 256;
        seg_kernel<<<blocks, 256>>>((const float2*)A, M);
    }
    {
        int smemBytes = 4096 * sizeof(float4) + TILE_M * sizeof(float); // 65664
        cudaFuncSetAttribute(final_kernel,
                             cudaFuncAttributeMaxDynamicSharedMemorySize,
                             smemBytes);
        int numTiles = (M + TILE_M - 1) / TILE_M;
        int blocks = 444;                 // ~3 per SM on 148 SMs
        if (blocks > numTiles) blocks = numTiles;
        final_kernel<<<blocks, 256, smemBytes>>>(
            (const float4*)A, vn, W1, b1, W2, b2, Wt, out, M, numTiles);
    }
}

// round 7
// speedup vs baseline: 3.5283x; 1.0200x over previous
#include <cuda_runtime.h>

#define CH 64
#define MMAX 50000
#define CAP 80
#define OVF_MAX 8192
#define TILE_M 32

// Allocation-free scratch.
__device__ float4 g_S4[MMAX * (CH / 4)];   // segment sums [M][64]
__device__ float  g_deg[MMAX];
__device__ int    g_cnt[MMAX];
__device__ int2   g_bin[MMAX * CAP];       // {src, __float_as_int(ew)}
__device__ int    g_ovf_n;
__device__ int2   g_ovf[OVF_MAX];          // {dst, src}
__device__ float  g_ovf_w[OVF_MAX];

#define FFMA2(acc, a, b) \
    asm("fma.rn.f32x2 %0, %1, %2, %0;" : "+l"(acc) : "l"(a), "l"(b))

__global__ void zero_kernel(int M) {
    int i = blockIdx.x * blockDim.x + threadIdx.x;
    if (i < M) g_cnt[i] = 0;
    if (i == 0) g_ovf_n = 0;
}

// Bin each edge under its destination. Packed 8B store (src + ew bits).
// Overflow (not expected at CAP=80) goes to a tiny list, applied by fixup.
__global__ void fill_kernel(const int2* __restrict__ idx2,
                            const int2* __restrict__ idx12,
                            const float2* __restrict__ ew2,
                            int E2, int E) {
    int t = blockIdx.x * blockDim.x + threadIdx.x;
    if (t >= E2) return;
    int2 ss = __ldg(&idx2[t]);
    int2 dd = __ldg(&idx12[t]);
    float2 ww = __ldg(&ew2[t]);
    int n = E - t * 2;   // handle odd tail
    #pragma unroll
    for (int j = 0; j < 2; j++) {
        if (j >= n) break;
        int src = j ? ss.y : ss.x;
        int dst = j ? dd.y : dd.x;
        float w = j ? ww.y : ww.x;
        int slot = atomicAdd(&g_cnt[dst], 1);
        if (slot < CAP) {
            g_bin[dst * CAP + slot] = make_int2(src, __float_as_int(w));
        } else {
            int o = atomicAdd(&g_ovf_n, 1);
            if (o < OVF_MAX) {
                g_ovf[o] = make_int2(dst, src);
                g_ovf_w[o] = w;
            }
        }
    }
}

// One warp per segment. Bin entries loaded with ONE coalesced int2 load per
// 32-chunk; src broadcast via shfl. Plain stores — no atomics, no pre-zero.
__global__ __launch_bounds__(256) void seg_kernel(const float2* __restrict__ A2,
                                                  int M) {
    int w = (blockIdx.x * blockDim.x + threadIdx.x) >> 5;
    int l = threadIdx.x & 31;
    if (w >= M) return;
    int cnt = g_cnt[w];
    if (cnt > CAP) cnt = CAP;

    float ax = 0.f, ay = 0.f, dl = 0.f;
    for (int c0 = 0; c0 < cnt; c0 += 32) {
        int nn = cnt - c0; if (nn > 32) nn = 32;
        int2 b = (l < nn) ? __ldg(&g_bin[w * CAP + c0 + l]) : make_int2(0, 0);
        if (l < nn) dl += __int_as_float(b.y);
        for (int j = 0; j < nn; j++) {
            int src = __shfl_sync(0xffffffffu, b.x, j);
            float2 v = __ldg(&A2[src * 32 + l]);
            ax += v.x; ay += v.y;
        }
    }
    #pragma unroll
    for (int o = 16; o; o >>= 1) dl += __shfl_xor_sync(0xffffffffu, dl, o);

    ((float2*)g_S4)[w * 32 + l] = make_float2(ax, ay);
    if (l == 0) g_deg[w] = dl;
}

// Apply overflow edges (normally zero of them) on top of seg's stores.
__global__ void fixup_kernel(const float4* __restrict__ A4) {
    int n = g_ovf_n;
    if (n > OVF_MAX) n = OVF_MAX;
    for (int t = threadIdx.x; t < n * 16; t += blockDim.x) {
        int e = t >> 4, q = t & 15;
        int2 ds = g_ovf[e];
        float4 v = __ldg(&A4[ds.y * 16 + q]);
        float4* p = &g_S4[ds.x * 16 + q];
        asm volatile("red.global.add.v4.f32 [%0], {%1,%2,%3,%4};"
                     :: "l"(p), "f"(v.x), "f"(v.y), "f"(v.z), "f"(v.w)
                     : "memory");
        if (q == 0) atomicAdd(&g_deg[ds.x], g_ovf_w[e]);
    }
}

// Epilogue with packed f32x2 FMAs. Per thread: 1 column x 8 rows; per kk-step
// the float4 operands are consumed as two natural b64 pairs -> fma.rn.f32x2
// with zero packing overhead. Accumulators are (even,odd) b64 pairs.
__global__ __launch_bounds__(256, 3) void final_kernel(
        const float4* __restrict__ A4,
        const int* __restrict__ vn,
        const float* __restrict__ W1,
        const float* __restrict__ b1,
        const float* __restrict__ W2,
        const float* __restrict__ b2,
        const float* __restrict__ Wt,   // weight, layout [k][c]
        float* __restrict__ out,
        int M, int numTiles) {
    extern __shared__ float4 sm[];
    float4* sW1v = sm;                   // [16][64]: kk -> W1[c][4kk..4kk+3]
    float4* sW2v = sm + 1024;            // [16][64]
    float4* sWv  = sm + 2048;            // [16][64]: kk -> Wt[4kk..4kk+3][c]
    float4* sX   = sm + 3072;            // [32][16]
    float4* sS   = sm + 3584;            // [32][16]
    float*  sDeg = (float*)(sm + 4096);  // [32]

    int tid = threadIdx.x;
    int c = tid & 63;
    int g = tid >> 6;
    float b1c = __ldg(&b1[c]);
    float b2c = __ldg(&b2[c]);

    const float4* W1v4 = (const float4*)W1;
    const float4* W2v4 = (const float4*)W2;
    for (int i = tid; i < 1024; i += 256) {
        int kk = i >> 6, cc = i & 63;
        sW1v[i] = __ldg(&W1v4[cc * 16 + kk]);   // W1 is [c][k] row-major
        sW2v[i] = __ldg(&W2v4[cc * 16 + kk]);
        int k0 = kk * 4;
        sWv[i] = make_float4(__ldg(&Wt[(k0 + 0) * CH + cc]),
                             __ldg(&Wt[(k0 + 1) * CH + cc]),
                             __ldg(&Wt[(k0 + 2) * CH + cc]),
                             __ldg(&Wt[(k0 + 3) * CH + cc]));
    }

    for (int tile = blockIdx.x; tile < numTiles; tile += gridDim.x) {
        int m0 = tile * TILE_M;
        __syncthreads();
        for (int i = tid; i < TILE_M * 16; i += 256) {
            int r = i >> 4, q = i & 15;
            int m = m0 + r;
            int mc = (m < M) ? m : 0;
            int rowA = (m < M) ? vn[m] : 0;
            sX[i] = __ldg(&A4[rowA * 16 + q]);
            sS[i] = g_S4[mc * 16 + q];
        }
        if (tid < TILE_M) {
            int m = m0 + tid;
            sDeg[tid] = (m < M) ? g_deg[m] : 0.f;
        }
        __syncthreads();

        unsigned long long a1[8], a2[8], a3[8];
        #pragma unroll
        for (int r = 0; r < 8; r++) { a1[r] = 0ull; a2[r] = 0ull; a3[r] = 0ull; }

        #pragma unroll
        for (int kk = 0; kk < 16; kk++) {
            ulonglong2 w1 = *(const ulonglong2*)&sW1v[kk * 64 + c];
            ulonglong2 w2 = *(const ulonglong2*)&sW2v[kk * 64 + c];
            ulonglong2 wv = *(const ulonglong2*)&sWv [kk * 64 + c];
            #pragma unroll
            for (int r = 0; r < 8; r++) {
                ulonglong2 x = *(const ulonglong2*)&sX[(g * 8 + r) * 16 + kk];
                ulonglong2 s = *(const ulonglong2*)&sS[(g * 8 + r) * 16 + kk];
                FFMA2(a1[r], x.x, w1.x); FFMA2(a1[r], x.y, w1.y);
                FFMA2(a2[r], x.x, w2.x); FFMA2(a2[r], x.y, w2.y);
                FFMA2(a3[r], s.x, wv.x); FFMA2(a3[r], s.y, wv.y);
            }
        }

        #pragma unroll
        for (int r = 0; r < 8; r++) {
            int m = m0 + g * 8 + r;
            if (m < M) {
                unsigned lo, hi;
                float s1, s2, s3;
                asm("mov.b64 {%0,%1}, %2;" : "=r"(lo), "=r"(hi) : "l"(a1[r]));
                s1 = __uint_as_float(lo) + __uint_as_float(hi);
                asm("mov.b64 {%0,%1}, %2;" : "=r"(lo), "=r"(hi) : "l"(a2[r]));
                s2 = __uint_as_float(lo) + __uint_as_float(hi);
                asm("mov.b64 {%0,%1}, %2;" : "=r"(lo), "=r"(hi) : "l"(a3[r]));
                s3 = __uint_as_float(lo) + __uint_as_float(hi);
                float d = sDeg[g * 8 + r];
                out[m * CH + c] = d * (s1 + b1c) + s3 + s2 + b2c;
            }
        }
    }
}

extern "C" void kernel_launch(void* const* d_in, const int* in_sizes, int n_in,
                              void* d_out, int out_size) {
    const float* A    = (const float*)d_in[0];   // [N, 64] f32
    const int*   vn   = (const int*)d_in[1];     // [M] int32
    const int*   idx  = (const int*)d_in[2];     // [E] int32
    const int*   idx1 = (const int*)d_in[3];     // [E] int32
    const float* ew   = (const float*)d_in[4];   // [E] f32
    const float* Wt   = (const float*)d_in[5];   // [64, 64] = [CIN][COUT]
    const float* W1   = (const float*)d_in[6];   // [64, 64] = [COUT][CIN]
    const float* b1   = (const float*)d_in[7];   // [64]
    const float* W2   = (const float*)d_in[8];   // [64, 64]
    const float* b2   = (const float*)d_in[9];   // [64]
    float* out = (float*)d_out;

    int M = in_sizes[1];
    int E = in_sizes[2];

    zero_kernel<<<(M + 255) / 256, 256>>>(M);
    {
        int E2 = (E + 1) / 2;
        fill_kernel<<<(E2 + 255) / 256, 256>>>(
            (const int2*)idx, (const int2*)idx1, (const float2*)ew, E2, E);
    }
    {
        int blocks = (M * 32 + 255) / 256;
        seg_kernel<<<blocks, 256>>>((const float2*)A, M);
    }
    fixup_kernel<<<1, 256>>>((const float4*)A);
    {
        int smemBytes = 4096 * sizeof(float4) + TILE_M * sizeof(float); // 65664
        cudaFuncSetAttribute(final_kernel,
                             cudaFuncAttributeMaxDynamicSharedMemorySize,
                             smemBytes);
        int numTiles = (M + TILE_M - 1) / TILE_M;
        int blocks = 444;
        if (blocks > numTiles) blocks = numTiles;
        final_kernel<<<blocks, 256, smemBytes>>>(
            (const float4*)A, vn, W1, b1, W2, b2, Wt, out, M, numTiles);
    }
}